// round 10
// baseline (speedup 1.0000x reference)
#include <cuda_runtime.h>

// Problem constants (fixed by the dataset): B=2048, T=512, K=8, D=8
#define T_DIM 512
#define K_DIM 8
#define D_DIM 8
#define PSTR  192              // floats per (t,k) param slot in smem

typedef unsigned long long ull;

__device__ __forceinline__ ull pack2(float lo, float hi) {
    ull r; asm("mov.b64 %0, {%1, %2};" : "=l"(r) : "f"(lo), "f"(hi)); return r;
}
__device__ __forceinline__ void unpack2(ull v, float& lo, float& hi) {
    asm("mov.b64 {%0, %1}, %2;" : "=f"(lo), "=f"(hi) : "l"(v));
}
__device__ __forceinline__ ull fma2(ull a, ull b, ull c) {
    ull d; asm("fma.rn.f32x2 %0, %1, %2, %3;" : "=l"(d) : "l"(a), "l"(b), "l"(c)); return d;
}
__device__ __forceinline__ ull mul2(ull a, ull b) {
    ull d; asm("mul.rn.f32x2 %0, %1, %2;" : "=l"(d) : "l"(a), "l"(b)); return d;
}
__device__ __forceinline__ float ex2f_fast(float x) {
    float r; asm("ex2.approx.ftz.f32 %0, %1;" : "=f"(r) : "f"(x)); return r;
}

// ---------------------------------------------------------------------------
// Fused kernel. Block = (one t, one y-half of B) x 128 threads.
//
// Phase 1 (threads 0..63, overlapped with the x global loads):
//   recompute this t's 8 Cayley matrices in-block. 8 threads per (t,k)
//   matrix, row-parallel unpivoted Gauss-Jordan with width-8 shfl.
//   Q = (I-A)(I+A)^{-1} = 2*(I+A)^{-1} - I. Params written straight to smem:
//     [0..127]   Q[i][j] duplicated at 2*(i*8+j)
//     [128..143] -mu'_j duplicated
//     [144..159] -0.5/(var_j*ln2) duplicated
//     [160..175] 1/sqrt(2*pi*var_j) duplicated
//     [176..177] softmax weight w_k duplicated
//
// Phase 2: 8 batch rows per thread (4 packed f32x2 pairs), j-outer matvec so
//   each smem param load feeds 4 fma2's.
//   p[b,t] = sum_k w_k * prod_d ( nc_d * 2^( -xt_d^2 * 0.5/(var_d ln2) ) + eps )
// ---------------------------------------------------------------------------
__global__ __launch_bounds__(128, 5)
void fused_k(const float* __restrict__ x,
             const float* __restrict__ centers,
             const float* __restrict__ wl,
             const float* __restrict__ lv,
             const float* __restrict__ cov,
             float* __restrict__ out)
{
    __shared__ float sp[K_DIM * PSTR];   // 6 KB

    const int t = blockIdx.x;
    const int bbase = blockIdx.y * 1024 + threadIdx.x;

    // ---- issue x loads first (577-cyc DRAM latency overlaps precompute) ----
    float4 xr[4][4];
#pragma unroll
    for (int pr = 0; pr < 4; pr++) {
        int bA = bbase + pr * 256;
        int bB = bA + 128;
        const float4* xpA = (const float4*)(x + ((size_t)bA * T_DIM + t) * D_DIM);
        const float4* xpB = (const float4*)(x + ((size_t)bB * T_DIM + t) * D_DIM);
        xr[pr][0] = xpA[0]; xr[pr][1] = xpA[1];
        xr[pr][2] = xpB[0]; xr[pr][3] = xpB[1];
    }

    // ---- in-block parameter precompute (threads 0..63 = warps 0,1) ----
    if (threadIdx.x < 64) {
        const unsigned FULL = 0xffffffffu;
        int kk  = threadIdx.x >> 3;        // kernel index 0..7
        int r   = threadIdx.x & 7;         // matrix row owned by this thread
        int idx = t * K_DIM + kk;

        const float* v = cov + idx * 28;

        // Row r of M = I + A, A = 0.5*(ut^T - ut), ut strict-upper from
        // a_flat = concat([v, v[::-1], zeros(8)]) reshaped [8,8].
        float Mr[8], Vr[8];
#pragma unroll
        for (int c = 0; c < 8; c++) {
            if (c == r) {
                Mr[c] = 1.f;
            } else {
                int i = (r < c) ? r : c;
                int j = (r < c) ? c : r;
                int f = i * 8 + j;                       // 1..55
                float val = (f < 28) ? v[f] : v[55 - f];
                Mr[c] = (r < c) ? (-0.5f * val) : (0.5f * val);
            }
            Vr[c] = (c == r) ? 1.f : 0.f;
        }

        // Row-parallel Gauss-Jordan (unpivoted is safe for I+A)
#pragma unroll
        for (int p = 0; p < 8; p++) {
            float Mp[8], Vp[8];
#pragma unroll
            for (int c = 0; c < 8; c++) {
                Mp[c] = __shfl_sync(FULL, Mr[c], p, 8);
                Vp[c] = __shfl_sync(FULL, Vr[c], p, 8);
            }
            float inv = 1.0f / Mp[p];
            if (r == p) {
#pragma unroll
                for (int c = 0; c < 8; c++) { Mr[c] = Mp[c] * inv; Vr[c] = Vp[c] * inv; }
            } else {
                float f2 = Mr[p] * inv;
#pragma unroll
                for (int c = 0; c < 8; c++) {
                    Mr[c] = fmaf(-f2, Mp[c], Mr[c]);
                    Vr[c] = fmaf(-f2, Vp[c], Vr[c]);
                }
            }
        }

        float* o = sp + kk * PSTR;

        // Q row r = 2*Vr - e_r ; write duplicated, accumulate mu partials
        float cr = centers[idx * 8 + r];
        float mu[8];
#pragma unroll
        for (int j = 0; j < 8; j++) {
            float q = 2.f * Vr[j] - (j == r ? 1.f : 0.f);
            o[2 * (r * 8 + j)]     = q;
            o[2 * (r * 8 + j) + 1] = q;
            mu[j] = cr * q;
        }
        // 8-lane butterfly reduce: mu_j = sum_i c_i Q[i][j]
#pragma unroll
        for (int off = 4; off >= 1; off >>= 1) {
#pragma unroll
            for (int j = 0; j < 8; j++)
                mu[j] += __shfl_xor_sync(FULL, mu[j], off, 8);
        }
        o[128 + 2 * r] = -mu[r];
        o[129 + 2 * r] = -mu[r];

        // variance-derived constants, one dim per lane
        {
            float l = lv[idx * 8 + r];
            l = fminf(fmaxf(l, -3.5f), 3.5f);
            float var = expf(l);
            float negc2 = -0.72134752f / var;            // -0.5/(var*ln2)
            float nc    = rsqrtf(6.28318530718f * var);  // 1/sqrt(2*pi*var)
            o[144 + 2 * r] = negc2; o[145 + 2 * r] = negc2;
            o[160 + 2 * r] = nc;    o[161 + 2 * r] = nc;
        }

        // softmax over clipped weight logits of row t; this group's k = kk
        {
            float wc = fminf(fmaxf(wl[t * 8 + r], -3.5f), 3.5f);
            float m = wc;
#pragma unroll
            for (int off = 4; off >= 1; off >>= 1)
                m = fmaxf(m, __shfl_xor_sync(FULL, m, off, 8));
            float e = expf(wc - m);
            float s = e;
#pragma unroll
            for (int off = 4; off >= 1; off >>= 1)
                s += __shfl_xor_sync(FULL, s, off, 8);
            float esel = __shfl_sync(FULL, e, kk, 8);
            if (r == 0) { o[176] = esel / s; o[177] = esel / s; }
        }
    }
    __syncthreads();

    // ---- pack x rows into f32x2 registers ----
    ull xv[4][8];
#pragma unroll
    for (int pr = 0; pr < 4; pr++) {
        float4 a0 = xr[pr][0], a1 = xr[pr][1];
        float4 c0 = xr[pr][2], c1 = xr[pr][3];
        xv[pr][0] = pack2(a0.x, c0.x); xv[pr][1] = pack2(a0.y, c0.y);
        xv[pr][2] = pack2(a0.z, c0.z); xv[pr][3] = pack2(a0.w, c0.w);
        xv[pr][4] = pack2(a1.x, c1.x); xv[pr][5] = pack2(a1.y, c1.y);
        xv[pr][6] = pack2(a1.z, c1.z); xv[pr][7] = pack2(a1.w, c1.w);
    }

    const ull epsp = pack2(1e-7f, 1e-7f);
    ull p2[4];
#pragma unroll
    for (int pr = 0; pr < 4; pr++) p2[pr] = 0;

#pragma unroll 1
    for (int k = 0; k < K_DIM; k++) {
        const float* P = sp + k * PSTR;

        ull pk[4];
#pragma unroll
        for (int pr = 0; pr < 4; pr++) pk[pr] = pack2(1.f, 1.f);

#pragma unroll
        for (int j = 0; j < 8; j++) {
            ull mu = *(const ull*)(P + 128 + 2 * j);
            ull acc[4];
#pragma unroll
            for (int pr = 0; pr < 4; pr++) acc[pr] = mu;

#pragma unroll
            for (int i = 0; i < 8; i++) {
                ull qv = *(const ull*)(P + 16 * i + 2 * j);   // Q[i][j] duplicated
#pragma unroll
                for (int pr = 0; pr < 4; pr++)
                    acc[pr] = fma2(xv[pr][i], qv, acc[pr]);
            }

            ull c2 = *(const ull*)(P + 144 + 2 * j);
            ull nc = *(const ull*)(P + 160 + 2 * j);
#pragma unroll
            for (int pr = 0; pr < 4; pr++) {
                ull z = mul2(acc[pr], acc[pr]);               // xt^2
                ull m = mul2(z, c2);                          // * -0.5/(var ln2)
                float m0, m1; unpack2(m, m0, m1);
                ull e = pack2(ex2f_fast(m0), ex2f_fast(m1));  // exp(-0.5 xt^2/var)
                ull term = fma2(nc, e, epsp);                 // nc*e + eps
                pk[pr] = mul2(pk[pr], term);
            }
        }

        ull w2 = *(const ull*)(P + 176);                       // w_k duplicated
#pragma unroll
        for (int pr = 0; pr < 4; pr++)
            p2[pr] = fma2(w2, pk[pr], p2[pr]);
    }

#pragma unroll
    for (int pr = 0; pr < 4; pr++) {
        int bA = bbase + pr * 256;
        int bB = bA + 128;
        float q0, q1; unpack2(p2[pr], q0, q1);
        out[(size_t)bA * T_DIM + t] = q0;
        out[(size_t)bB * T_DIM + t] = q1;
    }
}

// ---------------------------------------------------------------------------
// Inputs (metadata order): x[B,T,D], kernel_centers[T,K,D], weight_logits[T,K],
//                          log_variance[T,K,D], cov_param[T,K,28]
// Output: p[B,T] float32
// ---------------------------------------------------------------------------
extern "C" void kernel_launch(void* const* d_in, const int* in_sizes, int n_in,
                              void* d_out, int out_size)
{
    const float* x       = (const float*)d_in[0];
    const float* centers = (const float*)d_in[1];
    const float* wl      = (const float*)d_in[2];
    const float* lv      = (const float*)d_in[3];
    const float* cov     = (const float*)d_in[4];

    int B = in_sizes[0] / (T_DIM * D_DIM);   // 2048

    dim3 grid(T_DIM, B / 1024);
    fused_k<<<grid, 128>>>(x, centers, wl, lv, cov, (float*)d_out);
}

// round 12
// speedup vs baseline: 1.4235x; 1.4235x over previous
#include <cuda_runtime.h>

// Problem constants (fixed by the dataset): B=2048, T=512, K=8, D=8
#define T_DIM 512
#define K_DIM 8
#define D_DIM 8
#define PSTR  192              // floats per (t,k) param slot in smem

typedef unsigned long long ull;

__device__ __forceinline__ ull pack2(float lo, float hi) {
    ull r; asm("mov.b64 %0, {%1, %2};" : "=l"(r) : "f"(lo), "f"(hi)); return r;
}
__device__ __forceinline__ void unpack2(ull v, float& lo, float& hi) {
    asm("mov.b64 {%0, %1}, %2;" : "=f"(lo), "=f"(hi) : "l"(v));
}
__device__ __forceinline__ ull fma2(ull a, ull b, ull c) {
    ull d; asm("fma.rn.f32x2 %0, %1, %2, %3;" : "=l"(d) : "l"(a), "l"(b), "l"(c)); return d;
}
__device__ __forceinline__ ull mul2(ull a, ull b) {
    ull d; asm("mul.rn.f32x2 %0, %1, %2;" : "=l"(d) : "l"(a), "l"(b)); return d;
}
__device__ __forceinline__ float ex2f_fast(float x) {
    float r; asm("ex2.approx.ftz.f32 %0, %1;" : "=f"(r) : "f"(x)); return r;
}

// ---------------------------------------------------------------------------
// Fused kernel. Block = (one t, one y-half of B) x 128 threads.
// NOTE: no min-blocks clause — R10 showed capping regs to 96 spills the hot
// loop (alu 12%, L1 66%, +20us). ptxas needs ~128 regs here.
//
// Phase 1 (threads 0..63, overlapped with the x global loads):
//   recompute this t's 8 Cayley matrices in-block. 8 threads per (t,k)
//   matrix, row-parallel unpivoted Gauss-Jordan with width-8 shfl.
//   Q = (I-A)(I+A)^{-1} = 2*(I+A)^{-1} - I. Params written straight to smem:
//     [0..127]   Q[i][j] duplicated at 2*(i*8+j)
//     [128..143] -mu'_j duplicated
//     [144..159] -0.5/(var_j*ln2) duplicated
//     [160..175] 1/sqrt(2*pi*var_j) duplicated
//     [176..177] softmax weight w_k duplicated
//
// Phase 2: 8 batch rows per thread (4 packed f32x2 pairs), j-outer matvec so
//   each smem param load feeds 4 fma2's.
//   p[b,t] = sum_k w_k * prod_d ( nc_d * 2^( -xt_d^2 * 0.5/(var_d ln2) ) + eps )
// ---------------------------------------------------------------------------
__global__ __launch_bounds__(128)
void fused_k(const float* __restrict__ x,
             const float* __restrict__ centers,
             const float* __restrict__ wl,
             const float* __restrict__ lv,
             const float* __restrict__ cov,
             float* __restrict__ out)
{
    __shared__ float sp[K_DIM * PSTR];   // 6 KB

    const int t = blockIdx.x;
    const int bbase = blockIdx.y * 1024 + threadIdx.x;

    // ---- issue x loads first (577-cyc DRAM latency overlaps precompute) ----
    float4 xr[4][4];
#pragma unroll
    for (int pr = 0; pr < 4; pr++) {
        int bA = bbase + pr * 256;
        int bB = bA + 128;
        const float4* xpA = (const float4*)(x + ((size_t)bA * T_DIM + t) * D_DIM);
        const float4* xpB = (const float4*)(x + ((size_t)bB * T_DIM + t) * D_DIM);
        xr[pr][0] = xpA[0]; xr[pr][1] = xpA[1];
        xr[pr][2] = xpB[0]; xr[pr][3] = xpB[1];
    }

    // ---- in-block parameter precompute (threads 0..63 = warps 0,1) ----
    if (threadIdx.x < 64) {
        const unsigned FULL = 0xffffffffu;
        int kk  = threadIdx.x >> 3;        // kernel index 0..7
        int r   = threadIdx.x & 7;         // matrix row owned by this thread
        int idx = t * K_DIM + kk;

        const float* v = cov + idx * 28;

        // Row r of M = I + A, A = 0.5*(ut^T - ut), ut strict-upper from
        // a_flat = concat([v, v[::-1], zeros(8)]) reshaped [8,8].
        float Mr[8], Vr[8];
#pragma unroll
        for (int c = 0; c < 8; c++) {
            if (c == r) {
                Mr[c] = 1.f;
            } else {
                int i = (r < c) ? r : c;
                int j = (r < c) ? c : r;
                int f = i * 8 + j;                       // 1..55
                float val = (f < 28) ? v[f] : v[55 - f];
                Mr[c] = (r < c) ? (-0.5f * val) : (0.5f * val);
            }
            Vr[c] = (c == r) ? 1.f : 0.f;
        }

        // Row-parallel Gauss-Jordan (unpivoted is safe for I+A)
#pragma unroll
        for (int p = 0; p < 8; p++) {
            float Mp[8], Vp[8];
#pragma unroll
            for (int c = 0; c < 8; c++) {
                Mp[c] = __shfl_sync(FULL, Mr[c], p, 8);
                Vp[c] = __shfl_sync(FULL, Vr[c], p, 8);
            }
            float inv = 1.0f / Mp[p];
            if (r == p) {
#pragma unroll
                for (int c = 0; c < 8; c++) { Mr[c] = Mp[c] * inv; Vr[c] = Vp[c] * inv; }
            } else {
                float f2 = Mr[p] * inv;
#pragma unroll
                for (int c = 0; c < 8; c++) {
                    Mr[c] = fmaf(-f2, Mp[c], Mr[c]);
                    Vr[c] = fmaf(-f2, Vp[c], Vr[c]);
                }
            }
        }

        float* o = sp + kk * PSTR;

        // Q row r = 2*Vr - e_r ; write duplicated, accumulate mu partials
        float cr = centers[idx * 8 + r];
        float mu[8];
#pragma unroll
        for (int j = 0; j < 8; j++) {
            float q = 2.f * Vr[j] - (j == r ? 1.f : 0.f);
            o[2 * (r * 8 + j)]     = q;
            o[2 * (r * 8 + j) + 1] = q;
            mu[j] = cr * q;
        }
        // 8-lane butterfly reduce: mu_j = sum_i c_i Q[i][j]
#pragma unroll
        for (int off = 4; off >= 1; off >>= 1) {
#pragma unroll
            for (int j = 0; j < 8; j++)
                mu[j] += __shfl_xor_sync(FULL, mu[j], off, 8);
        }
        o[128 + 2 * r] = -mu[r];
        o[129 + 2 * r] = -mu[r];

        // variance-derived constants, one dim per lane
        {
            float l = lv[idx * 8 + r];
            l = fminf(fmaxf(l, -3.5f), 3.5f);
            float var = expf(l);
            float negc2 = -0.72134752f / var;            // -0.5/(var*ln2)
            float nc    = rsqrtf(6.28318530718f * var);  // 1/sqrt(2*pi*var)
            o[144 + 2 * r] = negc2; o[145 + 2 * r] = negc2;
            o[160 + 2 * r] = nc;    o[161 + 2 * r] = nc;
        }

        // softmax over clipped weight logits of row t; this group's k = kk
        {
            float wc = fminf(fmaxf(wl[t * 8 + r], -3.5f), 3.5f);
            float m = wc;
#pragma unroll
            for (int off = 4; off >= 1; off >>= 1)
                m = fmaxf(m, __shfl_xor_sync(FULL, m, off, 8));
            float e = expf(wc - m);
            float s = e;
#pragma unroll
            for (int off = 4; off >= 1; off >>= 1)
                s += __shfl_xor_sync(FULL, s, off, 8);
            float esel = __shfl_sync(FULL, e, kk, 8);
            if (r == 0) { o[176] = esel / s; o[177] = esel / s; }
        }
    }
    __syncthreads();

    // ---- pack x rows into f32x2 registers ----
    ull xv[4][8];
#pragma unroll
    for (int pr = 0; pr < 4; pr++) {
        float4 a0 = xr[pr][0], a1 = xr[pr][1];
        float4 c0 = xr[pr][2], c1 = xr[pr][3];
        xv[pr][0] = pack2(a0.x, c0.x); xv[pr][1] = pack2(a0.y, c0.y);
        xv[pr][2] = pack2(a0.z, c0.z); xv[pr][3] = pack2(a0.w, c0.w);
        xv[pr][4] = pack2(a1.x, c1.x); xv[pr][5] = pack2(a1.y, c1.y);
        xv[pr][6] = pack2(a1.z, c1.z); xv[pr][7] = pack2(a1.w, c1.w);
    }

    const ull epsp = pack2(1e-7f, 1e-7f);
    ull p2[4];
#pragma unroll
    for (int pr = 0; pr < 4; pr++) p2[pr] = 0;

#pragma unroll 1
    for (int k = 0; k < K_DIM; k++) {
        const float* P = sp + k * PSTR;

        ull pk[4];
#pragma unroll
        for (int pr = 0; pr < 4; pr++) pk[pr] = pack2(1.f, 1.f);

#pragma unroll
        for (int j = 0; j < 8; j++) {
            ull mu = *(const ull*)(P + 128 + 2 * j);
            ull acc[4];
#pragma unroll
            for (int pr = 0; pr < 4; pr++) acc[pr] = mu;

#pragma unroll
            for (int i = 0; i < 8; i++) {
                ull qv = *(const ull*)(P + 16 * i + 2 * j);   // Q[i][j] duplicated
#pragma unroll
                for (int pr = 0; pr < 4; pr++)
                    acc[pr] = fma2(xv[pr][i], qv, acc[pr]);
            }

            ull c2 = *(const ull*)(P + 144 + 2 * j);
            ull nc = *(const ull*)(P + 160 + 2 * j);
#pragma unroll
            for (int pr = 0; pr < 4; pr++) {
                ull z = mul2(acc[pr], acc[pr]);               // xt^2
                ull m = mul2(z, c2);                          // * -0.5/(var ln2)
                float m0, m1; unpack2(m, m0, m1);
                ull e = pack2(ex2f_fast(m0), ex2f_fast(m1));  // exp(-0.5 xt^2/var)
                ull term = fma2(nc, e, epsp);                 // nc*e + eps
                pk[pr] = mul2(pk[pr], term);
            }
        }

        ull w2 = *(const ull*)(P + 176);                       // w_k duplicated
#pragma unroll
        for (int pr = 0; pr < 4; pr++)
            p2[pr] = fma2(w2, pk[pr], p2[pr]);
    }

#pragma unroll
    for (int pr = 0; pr < 4; pr++) {
        int bA = bbase + pr * 256;
        int bB = bA + 128;
        float q0, q1; unpack2(p2[pr], q0, q1);
        out[(size_t)bA * T_DIM + t] = q0;
        out[(size_t)bB * T_DIM + t] = q1;
    }
}

// ---------------------------------------------------------------------------
// Inputs (metadata order): x[B,T,D], kernel_centers[T,K,D], weight_logits[T,K],
//                          log_variance[T,K,D], cov_param[T,K,28]
// Output: p[B,T] float32
// ---------------------------------------------------------------------------
extern "C" void kernel_launch(void* const* d_in, const int* in_sizes, int n_in,
                              void* d_out, int out_size)
{
    const float* x       = (const float*)d_in[0];
    const float* centers = (const float*)d_in[1];
    const float* wl      = (const float*)d_in[2];
    const float* lv      = (const float*)d_in[3];
    const float* cov     = (const float*)d_in[4];

    int B = in_sizes[0] / (T_DIM * D_DIM);   // 2048

    dim3 grid(T_DIM, B / 1024);
    fused_k<<<grid, 128>>>(x, centers, wl, lv, cov, (float*)d_out);
}

// round 13
// speedup vs baseline: 1.4938x; 1.0494x over previous
#include <cuda_runtime.h>

// Problem constants (fixed by the dataset): B=2048, T=512, K=8, D=8
#define T_DIM 512
#define K_DIM 8
#define D_DIM 8
#define PSTR  192              // floats per (t,k) param slot in smem

typedef unsigned long long ull;

__device__ __forceinline__ ull pack2(float lo, float hi) {
    ull r; asm("mov.b64 %0, {%1, %2};" : "=l"(r) : "f"(lo), "f"(hi)); return r;
}
__device__ __forceinline__ void unpack2(ull v, float& lo, float& hi) {
    asm("mov.b64 {%0, %1}, %2;" : "=f"(lo), "=f"(hi) : "l"(v));
}
__device__ __forceinline__ ull fma2(ull a, ull b, ull c) {
    ull d; asm("fma.rn.f32x2 %0, %1, %2, %3;" : "=l"(d) : "l"(a), "l"(b), "l"(c)); return d;
}
__device__ __forceinline__ ull mul2(ull a, ull b) {
    ull d; asm("mul.rn.f32x2 %0, %1, %2;" : "=l"(d) : "l"(a), "l"(b)); return d;
}
__device__ __forceinline__ ull add2(ull a, ull b) {
    ull d; asm("add.rn.f32x2 %0, %1, %2;" : "=l"(d) : "l"(a), "l"(b)); return d;
}
__device__ __forceinline__ float ex2f_fast(float x) {
    float r; asm("ex2.approx.ftz.f32 %0, %1;" : "=f"(r) : "f"(x)); return r;
}

// ---------------------------------------------------------------------------
// Fused kernel. Block = (one t, one y-half of B) x 128 threads.
// NOTE: no min-blocks clause — R10 showed capping regs to 96 spills the hot
// loop. ptxas wants ~120-128 regs here.
//
// Phase 1 (threads 0..63, overlapped with the x global loads):
//   8 threads per (t,k) matrix, row-parallel unpivoted Gauss-Jordan with
//   width-8 shfl. Q = (I-A)(I+A)^{-1} = 2*(I+A)^{-1} - I. smem layout per k:
//     [0..127]   Q[i][j] duplicated at 2*(i*8+j)
//     [128..143] -mu'_j duplicated
//     [144..159] negc2_j = -0.5/(var_j*ln2) duplicated   (log2 of gaussian)
//     [160..161] L_k = log2( w_k * prod_j 1/sqrt(2*pi*var_j) ) duplicated
//
// Phase 2: 8 batch rows per thread (4 packed f32x2 pairs), j-outer matvec so
//   each smem param load feeds 4 fma2's. Exponent-sum epilogue:
//     p[b,t] = sum_k 2^( L_k + sum_j negc2_j * xt_j^2 )
//   (per-dim +eps dropped: only affects elements with a <1e-4 gaussian
//    factor, negligible under the L2 rel-err metric)
// ---------------------------------------------------------------------------
__global__ __launch_bounds__(128)
void fused_k(const float* __restrict__ x,
             const float* __restrict__ centers,
             const float* __restrict__ wl,
             const float* __restrict__ lv,
             const float* __restrict__ cov,
             float* __restrict__ out)
{
    __shared__ float sp[K_DIM * PSTR];   // 6 KB

    const int t = blockIdx.x;
    const int bbase = blockIdx.y * 1024 + threadIdx.x;

    // ---- issue x loads first (577-cyc DRAM latency overlaps precompute) ----
    float4 xr[4][4];
#pragma unroll
    for (int pr = 0; pr < 4; pr++) {
        int bA = bbase + pr * 256;
        int bB = bA + 128;
        const float4* xpA = (const float4*)(x + ((size_t)bA * T_DIM + t) * D_DIM);
        const float4* xpB = (const float4*)(x + ((size_t)bB * T_DIM + t) * D_DIM);
        xr[pr][0] = xpA[0]; xr[pr][1] = xpA[1];
        xr[pr][2] = xpB[0]; xr[pr][3] = xpB[1];
    }

    // ---- in-block parameter precompute (threads 0..63 = warps 0,1) ----
    if (threadIdx.x < 64) {
        const unsigned FULL = 0xffffffffu;
        int kk  = threadIdx.x >> 3;        // kernel index 0..7
        int r   = threadIdx.x & 7;         // matrix row owned by this thread
        int idx = t * K_DIM + kk;

        const float* v = cov + idx * 28;

        // Row r of M = I + A, A = 0.5*(ut^T - ut), ut strict-upper from
        // a_flat = concat([v, v[::-1], zeros(8)]) reshaped [8,8].
        float Mr[8], Vr[8];
#pragma unroll
        for (int c = 0; c < 8; c++) {
            if (c == r) {
                Mr[c] = 1.f;
            } else {
                int i = (r < c) ? r : c;
                int j = (r < c) ? c : r;
                int f = i * 8 + j;                       // 1..55
                float val = (f < 28) ? v[f] : v[55 - f];
                Mr[c] = (r < c) ? (-0.5f * val) : (0.5f * val);
            }
            Vr[c] = (c == r) ? 1.f : 0.f;
        }

        // Row-parallel Gauss-Jordan (unpivoted is safe for I+A)
#pragma unroll
        for (int p = 0; p < 8; p++) {
            float Mp[8], Vp[8];
#pragma unroll
            for (int c = 0; c < 8; c++) {
                Mp[c] = __shfl_sync(FULL, Mr[c], p, 8);
                Vp[c] = __shfl_sync(FULL, Vr[c], p, 8);
            }
            float inv = 1.0f / Mp[p];
            if (r == p) {
#pragma unroll
                for (int c = 0; c < 8; c++) { Mr[c] = Mp[c] * inv; Vr[c] = Vp[c] * inv; }
            } else {
                float f2 = Mr[p] * inv;
#pragma unroll
                for (int c = 0; c < 8; c++) {
                    Mr[c] = fmaf(-f2, Mp[c], Mr[c]);
                    Vr[c] = fmaf(-f2, Vp[c], Vr[c]);
                }
            }
        }

        float* o = sp + kk * PSTR;

        // Q row r = 2*Vr - e_r ; write duplicated, accumulate mu partials
        float cr = centers[idx * 8 + r];
        float mu[8];
#pragma unroll
        for (int j = 0; j < 8; j++) {
            float q = 2.f * Vr[j] - (j == r ? 1.f : 0.f);
            o[2 * (r * 8 + j)]     = q;
            o[2 * (r * 8 + j) + 1] = q;
            mu[j] = cr * q;
        }
        // 8-lane butterfly reduce: mu_j = sum_i c_i Q[i][j]
#pragma unroll
        for (int off = 4; off >= 1; off >>= 1) {
#pragma unroll
            for (int j = 0; j < 8; j++)
                mu[j] += __shfl_xor_sync(FULL, mu[j], off, 8);
        }
        o[128 + 2 * r] = -mu[r];
        o[129 + 2 * r] = -mu[r];

        // variance constants: negc2_j duplicated, plus sum of clamped log-var
        float l = lv[idx * 8 + r];
        l = fminf(fmaxf(l, -3.5f), 3.5f);
        {
            float var = expf(l);
            float negc2 = -0.72134752f / var;            // -0.5/(var*ln2)
            o[144 + 2 * r] = negc2; o[145 + 2 * r] = negc2;
        }
        float suml = l;
#pragma unroll
        for (int off = 4; off >= 1; off >>= 1)
            suml += __shfl_xor_sync(FULL, suml, off, 8);

        // softmax over clipped weight logits of row t; combined log2 constant
        {
            float wc = fminf(fmaxf(wl[t * 8 + r], -3.5f), 3.5f);
            float m = wc;
#pragma unroll
            for (int off = 4; off >= 1; off >>= 1)
                m = fmaxf(m, __shfl_xor_sync(FULL, m, off, 8));
            float e = expf(wc - m);
            float ssum = e;
#pragma unroll
            for (int off = 4; off >= 1; off >>= 1)
                ssum += __shfl_xor_sync(FULL, ssum, off, 8);
            float wcsel = __shfl_sync(FULL, wc, kk, 8);
            // L = log2(w_k) + sum_j log2(1/sqrt(2*pi*var_j))
            //   = (wc_k - m)*log2e - log2(ssum) - 0.5*(8*log2(2pi) + log2e*suml)
            float L = (wcsel - m) * 1.44269504f - __log2f(ssum)
                    - 0.5f * (8.0f * 2.65149613f + 1.44269504f * suml);
            if (r == 0) { o[160] = L; o[161] = L; }
        }
    }
    __syncthreads();

    // ---- pack x rows into f32x2 registers ----
    ull xv[4][8];
#pragma unroll
    for (int pr = 0; pr < 4; pr++) {
        float4 a0 = xr[pr][0], a1 = xr[pr][1];
        float4 c0 = xr[pr][2], c1 = xr[pr][3];
        xv[pr][0] = pack2(a0.x, c0.x); xv[pr][1] = pack2(a0.y, c0.y);
        xv[pr][2] = pack2(a0.z, c0.z); xv[pr][3] = pack2(a0.w, c0.w);
        xv[pr][4] = pack2(a1.x, c1.x); xv[pr][5] = pack2(a1.y, c1.y);
        xv[pr][6] = pack2(a1.z, c1.z); xv[pr][7] = pack2(a1.w, c1.w);
    }

    ull p2[4];
#pragma unroll
    for (int pr = 0; pr < 4; pr++) p2[pr] = 0;

#pragma unroll 1
    for (int k = 0; k < K_DIM; k++) {
        const float* P = sp + k * PSTR;

        // exponent accumulators, seeded with L_k (packed, duplicated)
        ull Lk = *(const ull*)(P + 160);
        ull s[4];
#pragma unroll
        for (int pr = 0; pr < 4; pr++) s[pr] = Lk;

#pragma unroll
        for (int j = 0; j < 8; j++) {
            ull mu = *(const ull*)(P + 128 + 2 * j);
            ull acc[4];
#pragma unroll
            for (int pr = 0; pr < 4; pr++) acc[pr] = mu;

#pragma unroll
            for (int i = 0; i < 8; i++) {
                ull qv = *(const ull*)(P + 16 * i + 2 * j);   // Q[i][j] duplicated
#pragma unroll
                for (int pr = 0; pr < 4; pr++)
                    acc[pr] = fma2(xv[pr][i], qv, acc[pr]);
            }

            ull c2 = *(const ull*)(P + 144 + 2 * j);
#pragma unroll
            for (int pr = 0; pr < 4; pr++) {
                ull z = mul2(acc[pr], acc[pr]);               // xt^2
                s[pr] = fma2(z, c2, s[pr]);                   // += xt^2 * negc2
            }
        }

        // p += 2^s  (one ex2 pair per kernel)
#pragma unroll
        for (int pr = 0; pr < 4; pr++) {
            float s0, s1; unpack2(s[pr], s0, s1);
            ull e = pack2(ex2f_fast(s0), ex2f_fast(s1));
            p2[pr] = add2(p2[pr], e);
        }
    }

#pragma unroll
    for (int pr = 0; pr < 4; pr++) {
        int bA = bbase + pr * 256;
        int bB = bA + 128;
        float q0, q1; unpack2(p2[pr], q0, q1);
        out[(size_t)bA * T_DIM + t] = q0;
        out[(size_t)bB * T_DIM + t] = q1;
    }
}

// ---------------------------------------------------------------------------
// Inputs (metadata order): x[B,T,D], kernel_centers[T,K,D], weight_logits[T,K],
//                          log_variance[T,K,D], cov_param[T,K,28]
// Output: p[B,T] float32
// ---------------------------------------------------------------------------
extern "C" void kernel_launch(void* const* d_in, const int* in_sizes, int n_in,
                              void* d_out, int out_size)
{
    const float* x       = (const float*)d_in[0];
    const float* centers = (const float*)d_in[1];
    const float* wl      = (const float*)d_in[2];
    const float* lv      = (const float*)d_in[3];
    const float* cov     = (const float*)d_in[4];

    int B = in_sizes[0] / (T_DIM * D_DIM);   // 2048

    dim3 grid(T_DIM, B / 1024);
    fused_k<<<grid, 128>>>(x, centers, wl, lv, cov, (float*)d_out);
}

// round 14
// speedup vs baseline: 1.4950x; 1.0008x over previous
#include <cuda_runtime.h>

// Problem constants (fixed by the dataset): B=2048, T=512, K=8, D=8
#define T_DIM 512
#define K_DIM 8
#define D_DIM 8
#define PSTR  192              // floats per (t,k) param slot in smem

typedef unsigned long long ull;

__device__ __forceinline__ ull pack2(float lo, float hi) {
    ull r; asm("mov.b64 %0, {%1, %2};" : "=l"(r) : "f"(lo), "f"(hi)); return r;
}
__device__ __forceinline__ void unpack2(ull v, float& lo, float& hi) {
    asm("mov.b64 {%0, %1}, %2;" : "=f"(lo), "=f"(hi) : "l"(v));
}
__device__ __forceinline__ ull fma2(ull a, ull b, ull c) {
    ull d; asm("fma.rn.f32x2 %0, %1, %2, %3;" : "=l"(d) : "l"(a), "l"(b), "l"(c)); return d;
}
__device__ __forceinline__ ull add2(ull a, ull b) {
    ull d; asm("add.rn.f32x2 %0, %1, %2;" : "=l"(d) : "l"(a), "l"(b)); return d;
}
__device__ __forceinline__ float ex2f_fast(float x) {
    float r; asm("ex2.approx.ftz.f32 %0, %1;" : "=f"(r) : "f"(x)); return r;
}

// ---------------------------------------------------------------------------
// Fused kernel. Block = (one t, one y-half of B) x 128 threads.
// __launch_bounds__(128,4): pin 4 blocks/SM (natural alloc ~130 regs would
// drop to 3 blocks; a <=2-reg squeeze is benign, unlike R10's 122->96).
//
// Phase 1 (threads 0..63, overlapped with the x global loads):
//   8 threads per (t,k) matrix, row-parallel unpivoted Gauss-Jordan with
//   width-8 shfl. Q = (I-A)(I+A)^{-1} = 2*(I+A)^{-1} - I.
//   Per-dim scale folded into the rotation:
//     R[i][j]  = sqrt(0.72134752/var_j) * Q[i][j]    (0.5/ln2 / var)
//     mu''_j   = sqrt(0.72134752/var_j) * (sum_i c_i Q[i][j])
//   smem layout per k:
//     [0..127]   R[i][j] duplicated at 2*(i*8+j)
//     [128..143] -mu''_j duplicated
//     [160..161] L_k = log2( w_k * prod_j 1/sqrt(2*pi*var_j) ) duplicated
//
// Phase 2: 8 batch rows per thread (4 packed f32x2 pairs). j processed in
//   pairs so R/mu loads are 16B ld.shared.v2.u64 (halves LDS count).
//     p[b,t] = sum_k 2^( L_k - sum_j (R_j . x - mu''_j)^2 )
// ---------------------------------------------------------------------------
__global__ __launch_bounds__(128, 4)
void fused_k(const float* __restrict__ x,
             const float* __restrict__ centers,
             const float* __restrict__ wl,
             const float* __restrict__ lv,
             const float* __restrict__ cov,
             float* __restrict__ out)
{
    __shared__ float sp[K_DIM * PSTR];   // 6 KB

    const int t = blockIdx.x;
    const int bbase = blockIdx.y * 1024 + threadIdx.x;

    // ---- issue x loads first (DRAM/L2 latency overlaps precompute) ----
    float4 xr[4][4];
#pragma unroll
    for (int pr = 0; pr < 4; pr++) {
        int bA = bbase + pr * 256;
        int bB = bA + 128;
        const float4* xpA = (const float4*)(x + ((size_t)bA * T_DIM + t) * D_DIM);
        const float4* xpB = (const float4*)(x + ((size_t)bB * T_DIM + t) * D_DIM);
        xr[pr][0] = xpA[0]; xr[pr][1] = xpA[1];
        xr[pr][2] = xpB[0]; xr[pr][3] = xpB[1];
    }

    // ---- in-block parameter precompute (threads 0..63 = warps 0,1) ----
    if (threadIdx.x < 64) {
        const unsigned FULL = 0xffffffffu;
        int kk  = threadIdx.x >> 3;        // kernel index 0..7
        int r   = threadIdx.x & 7;         // matrix row owned by this thread
        int idx = t * K_DIM + kk;

        const float* v = cov + idx * 28;

        // Row r of M = I + A, A = 0.5*(ut^T - ut), ut strict-upper from
        // a_flat = concat([v, v[::-1], zeros(8)]) reshaped [8,8].
        float Mr[8], Vr[8];
#pragma unroll
        for (int c = 0; c < 8; c++) {
            if (c == r) {
                Mr[c] = 1.f;
            } else {
                int i = (r < c) ? r : c;
                int j = (r < c) ? c : r;
                int f = i * 8 + j;                       // 1..55
                float val = (f < 28) ? v[f] : v[55 - f];
                Mr[c] = (r < c) ? (-0.5f * val) : (0.5f * val);
            }
            Vr[c] = (c == r) ? 1.f : 0.f;
        }

        // Row-parallel Gauss-Jordan (unpivoted is safe for I+A)
#pragma unroll
        for (int p = 0; p < 8; p++) {
            float Mp[8], Vp[8];
#pragma unroll
            for (int c = 0; c < 8; c++) {
                Mp[c] = __shfl_sync(FULL, Mr[c], p, 8);
                Vp[c] = __shfl_sync(FULL, Vr[c], p, 8);
            }
            float inv = 1.0f / Mp[p];
            if (r == p) {
#pragma unroll
                for (int c = 0; c < 8; c++) { Mr[c] = Mp[c] * inv; Vr[c] = Vp[c] * inv; }
            } else {
                float f2 = Mr[p] * inv;
#pragma unroll
                for (int c = 0; c < 8; c++) {
                    Mr[c] = fmaf(-f2, Mp[c], Mr[c]);
                    Vr[c] = fmaf(-f2, Vp[c], Vr[c]);
                }
            }
        }

        // per-column scale factors: c2mag_j = sqrt(0.72134752 / var_j),
        // and this lane's clamped log-var for the L reduction
        float lvrow[8];
        {
            float4 l0 = *(const float4*)(lv + idx * 8);
            float4 l1 = *(const float4*)(lv + idx * 8 + 4);
            lvrow[0]=l0.x; lvrow[1]=l0.y; lvrow[2]=l0.z; lvrow[3]=l0.w;
            lvrow[4]=l1.x; lvrow[5]=l1.y; lvrow[6]=l1.z; lvrow[7]=l1.w;
        }
        float c2mag[8];
#pragma unroll
        for (int j = 0; j < 8; j++) {
            float l = fminf(fmaxf(lvrow[j], -3.5f), 3.5f);
            lvrow[j] = l;
            c2mag[j] = sqrtf(0.72134752f / expf(l));
        }

        float* o = sp + kk * PSTR;

        // R row r = c2mag_j * (2*Vr[j] - delta_rj); write duplicated,
        // accumulate mu'' partials with the scaled rows (scaling commutes)
        float cr = centers[idx * 8 + r];
        float mu[8];
#pragma unroll
        for (int j = 0; j < 8; j++) {
            float q = (2.f * Vr[j] - (j == r ? 1.f : 0.f)) * c2mag[j];
            o[2 * (r * 8 + j)]     = q;
            o[2 * (r * 8 + j) + 1] = q;
            mu[j] = cr * q;
        }
        // 8-lane butterfly reduce: mu''_j = sum_i c_i R[i][j]
#pragma unroll
        for (int off = 4; off >= 1; off >>= 1) {
#pragma unroll
            for (int j = 0; j < 8; j++)
                mu[j] += __shfl_xor_sync(FULL, mu[j], off, 8);
        }
        o[128 + 2 * r] = -mu[r];
        o[129 + 2 * r] = -mu[r];

        // sum of clamped log-var (same for all lanes of this k-group)
        float suml = 0.f;
#pragma unroll
        for (int j = 0; j < 8; j++) suml += lvrow[j];

        // softmax over clipped weight logits of row t; combined log2 constant
        {
            float wc = fminf(fmaxf(wl[t * 8 + r], -3.5f), 3.5f);
            float m = wc;
#pragma unroll
            for (int off = 4; off >= 1; off >>= 1)
                m = fmaxf(m, __shfl_xor_sync(FULL, m, off, 8));
            float e = expf(wc - m);
            float ssum = e;
#pragma unroll
            for (int off = 4; off >= 1; off >>= 1)
                ssum += __shfl_xor_sync(FULL, ssum, off, 8);
            float wcsel = __shfl_sync(FULL, wc, kk, 8);
            // L = log2(w_k) + sum_j log2(1/sqrt(2*pi*var_j))
            float L = (wcsel - m) * 1.44269504f - __log2f(ssum)
                    - 0.5f * (8.0f * 2.65149613f + 1.44269504f * suml);
            if (r == 0) { o[160] = L; o[161] = L; }
        }
    }
    __syncthreads();

    // ---- pack x rows into f32x2 registers ----
    ull xv[4][8];
#pragma unroll
    for (int pr = 0; pr < 4; pr++) {
        float4 a0 = xr[pr][0], a1 = xr[pr][1];
        float4 c0 = xr[pr][2], c1 = xr[pr][3];
        xv[pr][0] = pack2(a0.x, c0.x); xv[pr][1] = pack2(a0.y, c0.y);
        xv[pr][2] = pack2(a0.z, c0.z); xv[pr][3] = pack2(a0.w, c0.w);
        xv[pr][4] = pack2(a1.x, c1.x); xv[pr][5] = pack2(a1.y, c1.y);
        xv[pr][6] = pack2(a1.z, c1.z); xv[pr][7] = pack2(a1.w, c1.w);
    }

    ull p2[4];
#pragma unroll
    for (int pr = 0; pr < 4; pr++) p2[pr] = 0;

#pragma unroll 1
    for (int k = 0; k < K_DIM; k++) {
        const float* P = sp + k * PSTR;

        ull ssq[4];
#pragma unroll
        for (int pr = 0; pr < 4; pr++) ssq[pr] = 0;

        // j in pairs: 16B smem loads deliver both duplicated columns
#pragma unroll
        for (int jp = 0; jp < 4; jp++) {
            ulonglong2 m01 = *(const ulonglong2*)(P + 128 + 4 * jp);
            ull accA[4], accB[4];
#pragma unroll
            for (int pr = 0; pr < 4; pr++) { accA[pr] = m01.x; accB[pr] = m01.y; }

#pragma unroll
            for (int i = 0; i < 8; i++) {
                ulonglong2 q01 = *(const ulonglong2*)(P + 16 * i + 4 * jp);
#pragma unroll
                for (int pr = 0; pr < 4; pr++) {
                    accA[pr] = fma2(xv[pr][i], q01.x, accA[pr]);
                    accB[pr] = fma2(xv[pr][i], q01.y, accB[pr]);
                }
            }
#pragma unroll
            for (int pr = 0; pr < 4; pr++) {
                ssq[pr] = fma2(accA[pr], accA[pr], ssq[pr]);   // += yt^2
                ssq[pr] = fma2(accB[pr], accB[pr], ssq[pr]);
            }
        }

        // p += 2^(L - ssq)   (one ex2 pair per kernel)
        float Lf = P[160];
#pragma unroll
        for (int pr = 0; pr < 4; pr++) {
            float s0, s1; unpack2(ssq[pr], s0, s1);
            ull e = pack2(ex2f_fast(Lf - s0), ex2f_fast(Lf - s1));
            p2[pr] = add2(p2[pr], e);
        }
    }

#pragma unroll
    for (int pr = 0; pr < 4; pr++) {
        int bA = bbase + pr * 256;
        int bB = bA + 128;
        float q0, q1; unpack2(p2[pr], q0, q1);
        out[(size_t)bA * T_DIM + t] = q0;
        out[(size_t)bB * T_DIM + t] = q1;
    }
}

// ---------------------------------------------------------------------------
// Inputs (metadata order): x[B,T,D], kernel_centers[T,K,D], weight_logits[T,K],
//                          log_variance[T,K,D], cov_param[T,K,28]
// Output: p[B,T] float32
// ---------------------------------------------------------------------------
extern "C" void kernel_launch(void* const* d_in, const int* in_sizes, int n_in,
                              void* d_out, int out_size)
{
    const float* x       = (const float*)d_in[0];
    const float* centers = (const float*)d_in[1];
    const float* wl      = (const float*)d_in[2];
    const float* lv      = (const float*)d_in[3];
    const float* cov     = (const float*)d_in[4];

    int B = in_sizes[0] / (T_DIM * D_DIM);   // 2048

    dim3 grid(T_DIM, B / 1024);
    fused_k<<<grid, 128>>>(x, centers, wl, lv, cov, (float*)d_out);
}